// round 13
// baseline (speedup 1.0000x reference)
#include <cuda_runtime.h>
#include <cuda_fp16.h>
#include <math.h>
#include <stdint.h>

#define B_ 4
#define S_ 2048
#define E_ 1024
#define H_ 16
#define D_ 64

static const int MTOT = B_ * S_;          // 8192
#define NELEM (B_ * S_ * E_)              // 8388608
#define NW (E_ * E_)

// ---------------- scratch (__device__ globals; no allocs allowed) ----------
__device__ __half g_hA[NELEM];    // q-activation staging; later attention output
__device__ __half g_hKs[NELEM];   // k-activation staging
__device__ __half g_hT[NELEM];    // v-activation staging
__device__ __half g_W1[NW];       // Wq (single fp16)
__device__ __half g_W2[NW];       // Wk
__device__ __half g_W3[NW];       // Wv
__device__ __half g_W4[NW];       // Wo
__device__ __half g_Qh[NELEM];    // roped Q (single, 1/8 folded)
__device__ __half g_Kh[NELEM];    // roped K (single fp16)
__device__ __half g_Vs[NELEM];    // V (single fp16)
__device__ float2 g_rope[S_ * 32];  // (cos, sin) table per (s, i)
__device__ unsigned int g_ctr[8];

// ---------------- helpers --------------------------------------------------
__device__ __forceinline__ uint32_t smem_u32(const void* p) {
    uint32_t a;
    asm("{ .reg .u64 t; cvta.to.shared.u64 t, %1; cvt.u32.u64 %0, t; }"
        : "=r"(a) : "l"(p));
    return a;
}
__device__ __forceinline__ void cp16(uint32_t saddr, const void* g) {
    asm volatile("cp.async.cg.shared.global [%0], [%1], 16;"
                 :: "r"(saddr), "l"(g) : "memory");
}
__device__ __forceinline__ void ldsm4(uint32_t* r, uint32_t a) {
    asm volatile("ldmatrix.sync.aligned.m8n8.x4.shared.b16 {%0,%1,%2,%3}, [%4];"
                 : "=r"(r[0]), "=r"(r[1]), "=r"(r[2]), "=r"(r[3]) : "r"(a));
}
__device__ __forceinline__ void ldsm4t(uint32_t* r, uint32_t a) {
    asm volatile("ldmatrix.sync.aligned.m8n8.x4.trans.shared.b16 {%0,%1,%2,%3}, [%4];"
                 : "=r"(r[0]), "=r"(r[1]), "=r"(r[2]), "=r"(r[3]) : "r"(a));
}
__device__ __forceinline__ void mma16816(float* c, const uint32_t* a,
                                         const uint32_t* b) {
    asm volatile(
        "mma.sync.aligned.m16n8k16.row.col.f32.f16.f16.f32 "
        "{%0,%1,%2,%3}, {%4,%5,%6,%7}, {%8,%9}, {%0,%1,%2,%3};"
        : "+f"(c[0]), "+f"(c[1]), "+f"(c[2]), "+f"(c[3])
        : "r"(a[0]), "r"(a[1]), "r"(a[2]), "r"(a[3]), "r"(b[0]), "r"(b[1]));
}
__device__ __forceinline__ uint32_t pack2h(float x0, float x1) {
    __half2 h = __floats2half2_rn(x0, x1);
    return *(uint32_t*)&h;
}

// ---------------- setup: zero counters + rope table ------------------------
__global__ __launch_bounds__(256)
void setup_kernel() {
    int idx = blockIdx.x * 256 + threadIdx.x;   // 65536 threads
    if (idx < 8) g_ctr[idx] = 0;
    int s = idx >> 5;
    int i = idx & 31;
    float inv_freq = __expf(-(float)i * (logf(10000.0f) / 32.0f));
    float ang = (float)s * inv_freq;
    float sn, cs;
    sincosf(ang, &sn, &cs);
    g_rope[idx] = make_float2(cs, sn);
}

// ---------------- merged converts: 4 weights + 3 activations ---------------
#define WCHUNKS (4 * (NW / 8))       // 524288
#define ACHUNKS (3 * (NELEM / 8))    // 3145728
__global__ __launch_bounds__(256)
void conv_all(const float* __restrict__ W0, const float* __restrict__ W1,
              const float* __restrict__ W2, const float* __restrict__ W3,
              const float* __restrict__ Aq, const float* __restrict__ Ak,
              const float* __restrict__ Av) {
    int i = blockIdx.x * 256 + threadIdx.x;
    const float* src;
    __half* dst;
    int j;
    if (i < WCHUNKS) {
        int which = i >> 17;
        j = i & 0x1FFFF;
        src = which == 0 ? W0 : which == 1 ? W1 : which == 2 ? W2 : W3;
        dst = which == 0 ? g_W1 : which == 1 ? g_W2 : which == 2 ? g_W3 : g_W4;
    } else {
        int i2 = i - WCHUNKS;
        int which = i2 >> 20;
        j = i2 & 0xFFFFF;
        src = which == 0 ? Aq : which == 1 ? Ak : Av;
        dst = which == 0 ? g_hA : which == 1 ? g_hKs : g_hT;
    }
    float4 v0 = ((const float4*)src)[2 * j];
    float4 v1 = ((const float4*)src)[2 * j + 1];
    float f[8] = {v0.x, v0.y, v0.z, v0.w, v1.x, v1.y, v1.z, v1.w};
    uint32_t h[4];
#pragma unroll
    for (int p = 0; p < 4; p++) h[p] = pack2h(f[2 * p], f[2 * p + 1]);
    ((uint4*)dst)[j] = make_uint4(h[0], h[1], h[2], h[3]);
}

// ---------------- GEMM tile body (128x128, BK=64, 8 warps, 3-stage) -------
#define ROWB 144
#define TILEH (128 * ROWB)                 // 18432
#define STAGEH (2 * TILEH)                 // 36864
#define GEMM_SMEM (3 * STAGEH)             // 110592  (>= 128*132*4 = 67584)

__device__ __forceinline__ void load_stage2(
    uint32_t sb, int st, const __half* __restrict__ A,
    const __half* __restrict__ Bs, int bm, int bn, int k0, int tid) {
    uint32_t s0 = sb + st * STAGEH;
#pragma unroll
    for (int p = 0; p < 4; p++) {
        int chunk = tid + p * 256;
        int row = chunk >> 3;
        int c16 = chunk & 7;
        uint32_t soff = (uint32_t)(row * ROWB + c16 * 16);
        size_t ga = ((size_t)(bm + row) << 10) + k0 + c16 * 8;
        size_t gb = ((size_t)(bn + row) << 10) + k0 + c16 * 8;
        cp16(s0 + soff,         A + ga);
        cp16(s0 + TILEH + soff, Bs + gb);
    }
}

// MODE: 0 = fp32 out, 1 = fp16 out, 2 = rope->Qh (x0.125), 3 = rope->Kh
__device__ __forceinline__ void gemm_tile(
    char* smem, uint32_t sb, int tid, int lane, int wid,
    const __half* __restrict__ A, const __half* __restrict__ Bs,
    float* __restrict__ C, __half* __restrict__ Ch,
    int bm, int bn, int mode) {
    const int wm = wid >> 2;
    const int wn = wid & 3;

    float acc[4][4][4];
#pragma unroll
    for (int i = 0; i < 4; i++)
#pragma unroll
        for (int j = 0; j < 4; j++)
#pragma unroll
            for (int r = 0; r < 4; r++) acc[i][j][r] = 0.f;

    load_stage2(sb, 0, A, Bs, bm, bn, 0, tid);
    asm volatile("cp.async.commit_group;" ::: "memory");
    load_stage2(sb, 1, A, Bs, bm, bn, 64, tid);
    asm volatile("cp.async.commit_group;" ::: "memory");

    const int NCH = E_ / 64;   // 16
    int st = 0;
    for (int c = 0; c < NCH; c++) {
        if (c + 1 < NCH)
            asm volatile("cp.async.wait_group 1;" ::: "memory");
        else
            asm volatile("cp.async.wait_group 0;" ::: "memory");
        __syncthreads();
        if (c + 2 < NCH) {
            int sn = st + 2; if (sn >= 3) sn -= 3;
            load_stage2(sb, sn, A, Bs, bm, bn, (c + 2) * 64, tid);
            asm volatile("cp.async.commit_group;" ::: "memory");
        }

        const uint32_t s0 = sb + st * STAGEH;
        const uint32_t sA = s0, sB = s0 + TILEH;

#pragma unroll
        for (int ks = 0; ks < 64; ks += 16) {
            uint32_t bs[2][4];
            const int brow = wn * 32 + (lane & 7) + ((lane >> 4) & 1) * 8;
            const int bkk = ks + ((lane >> 3) & 1) * 8;
#pragma unroll
            for (int nb = 0; nb < 2; nb++)
                ldsm4(bs[nb], sB + (uint32_t)((brow + nb * 16) * ROWB + bkk * 2));
            const int arow = wm * 64 + (lane & 7) + ((lane >> 3) & 1) * 8;
            const int akk = ks + (lane >> 4) * 8;
#pragma unroll
            for (int mi = 0; mi < 4; mi++) {
                uint32_t a[4];
                ldsm4(a, sA + (uint32_t)((arow + mi * 16) * ROWB + akk * 2));
#pragma unroll
                for (int ni = 0; ni < 4; ni++)
                    mma16816(acc[mi][ni], a, &bs[ni >> 1][(ni & 1) * 2]);
            }
        }
        if (++st == 3) st = 0;
    }
    __syncthreads();   // mainloop smem dead; safe to reuse / next prologue

    const int r0 = wm * 64 + (lane >> 2);
    const int c0 = wn * 32 + (lane & 3) * 2;
    if (mode == 0) {
#pragma unroll
        for (int mi = 0; mi < 4; mi++)
#pragma unroll
            for (int ni = 0; ni < 4; ni++) {
                int row = bm + r0 + mi * 16;
                int col = bn + c0 + ni * 8;
                *(float2*)&C[(size_t)row * E_ + col] =
                    make_float2(acc[mi][ni][0], acc[mi][ni][1]);
                *(float2*)&C[(size_t)(row + 8) * E_ + col] =
                    make_float2(acc[mi][ni][2], acc[mi][ni][3]);
            }
    } else if (mode == 1) {
#pragma unroll
        for (int mi = 0; mi < 4; mi++)
#pragma unroll
            for (int ni = 0; ni < 4; ni++) {
                int row = bm + r0 + mi * 16;
                int col = bn + c0 + ni * 8;
                *(uint32_t*)&Ch[(size_t)row * E_ + col] =
                    pack2h(acc[mi][ni][0], acc[mi][ni][1]);
                *(uint32_t*)&Ch[(size_t)(row + 8) * E_ + col] =
                    pack2h(acc[mi][ni][2], acc[mi][ni][3]);
            }
    } else {
        // rope epilogue: stage fp32 tile in smem, apply rope, write fp16
        float* stg = (float*)smem;   // 128 x 132 floats
#pragma unroll
        for (int mi = 0; mi < 4; mi++)
#pragma unroll
            for (int ni = 0; ni < 4; ni++) {
                int row = r0 + mi * 16;
                int col = c0 + ni * 8;
                *(float2*)&stg[row * 132 + col] =
                    make_float2(acc[mi][ni][0], acc[mi][ni][1]);
                *(float2*)&stg[(row + 8) * 132 + col] =
                    make_float2(acc[mi][ni][2], acc[mi][ni][3]);
            }
        __syncthreads();

        const float scale = (mode == 2) ? 0.125f : 1.0f;
        const int row = tid >> 1;            // 0..127
        const int head = tid & 1;            // head within CTA tile
        const int gr = bm + row;
        const int s = gr & (S_ - 1);
        const float2* tab = g_rope + s * 32;
        const size_t gbase = (size_t)gr * E_ + bn + head * 64;
        const float* srow = stg + row * 132 + head * 64;
#pragma unroll
        for (int i0 = 0; i0 < 32; i0 += 4) {
            float x1[4], x2[4];
            *(float4*)x1 = *(const float4*)&srow[i0];
            *(float4*)x2 = *(const float4*)&srow[i0 + 32];
            __half lo[4], hi[4];
#pragma unroll
            for (int j = 0; j < 4; j++) {
                float2 cssn = tab[i0 + j];
                float y1 = (x1[j] * cssn.x - x2[j] * cssn.y) * scale;
                float y2 = (x2[j] * cssn.x + x1[j] * cssn.y) * scale;
                lo[j] = __float2half_rn(y1);
                hi[j] = __float2half_rn(y2);
            }
            *(uint2*)&Ch[gbase + i0]      = *(uint2*)lo;
            *(uint2*)&Ch[gbase + i0 + 32] = *(uint2*)hi;
        }
        __syncthreads();   // staging dead before next tile's loads
    }
}

// Persistent fused Q/K/V projections: 1536 tiles on g_ctr[0].
__global__ __launch_bounds__(256, 2)
void gemm_qkv() {
    extern __shared__ char smem[];
    const uint32_t sb = smem_u32(smem);
    const int tid = threadIdx.x;
    const int lane = tid & 31;
    const int wid = tid >> 5;
    __shared__ unsigned s_t;

    for (;;) {
        if (tid == 0) s_t = atomicAdd(&g_ctr[0], 1u);
        __syncthreads();
        unsigned t = s_t;
        __syncthreads();
        if (t >= 1536u) return;
        int which = t >> 9;
        int rem = t & 511;
        int bm = (rem >> 3) * 128, bn = (rem & 7) * 128;
        if (which == 0)
            gemm_tile(smem, sb, tid, lane, wid, g_hA, g_W1,
                      nullptr, g_Qh, bm, bn, 2);
        else if (which == 1)
            gemm_tile(smem, sb, tid, lane, wid, g_hKs, g_W2,
                      nullptr, g_Kh, bm, bn, 3);
        else
            gemm_tile(smem, sb, tid, lane, wid, g_hT, g_W3,
                      nullptr, g_Vs, bm, bn, 1);
    }
}

// Persistent output projection: 512 tiles on g_ctr[1].
__global__ __launch_bounds__(256, 2)
void gemm_o(float* __restrict__ out) {
    extern __shared__ char smem[];
    const uint32_t sb = smem_u32(smem);
    const int tid = threadIdx.x;
    const int lane = tid & 31;
    const int wid = tid >> 5;
    __shared__ unsigned s_t;

    for (;;) {
        if (tid == 0) s_t = atomicAdd(&g_ctr[1], 1u);
        __syncthreads();
        unsigned t = s_t;
        __syncthreads();
        if (t >= 512u) return;
        int bm = (t >> 3) * 128, bn = (t & 7) * 128;
        gemm_tile(smem, sb, tid, lane, wid, g_hA, g_W4,
                  out, nullptr, bm, bn, 0);
    }
}

// ---------------- tensor-core causal flash attention (all-single fp16) ----
#define AROWB 144
#define KVTILE (64 * AROWB)                 // 9216
#define KVSTAGE (2 * KVTILE)                // 18432
#define Q_OFF (3 * KVSTAGE)                 // 55296
#define ATTN_SMEM (Q_OFF + 128 * AROWB)     // 73728

__device__ __forceinline__ void load_kv(
    uint32_t sb, size_t rowbase, size_t headoff, int k0, int tid) {
#pragma unroll
    for (int p = 0; p < 2; p++) {
        int chunk = tid + p * 256;
        int row = chunk >> 3;
        int c8 = chunk & 7;
        size_t g = (rowbase + k0 + row) * E_ + headoff + c8 * 8;
        uint32_t so = (uint32_t)(row * AROWB + c8 * 16);
        cp16(sb + so,          g_Kh + g);
        cp16(sb + KVTILE + so, g_Vs + g);
    }
}

__global__ __launch_bounds__(256, 2)
void flash_attn_tc(__half* __restrict__ Oh) {
    extern __shared__ char smem[];
    const uint32_t sb = smem_u32(smem);
    const int tid = threadIdx.x;
    const int lane = tid & 31;
    const int w = tid >> 5;
    const int qt = gridDim.x - 1 - blockIdx.x;
    const int h = blockIdx.y;
    const int b = blockIdx.z;
    const int q0 = qt * 128;
    const size_t rowbase = (size_t)(b * S_);
    const size_t headoff = (size_t)h * D_;

#pragma unroll
    for (int p = 0; p < 4; p++) {
        int chunk = tid + p * 256;
        int row = chunk >> 3;
        int c8 = chunk & 7;
        size_t g = (rowbase + q0 + row) * E_ + headoff + c8 * 8;
        cp16(sb + Q_OFF + (uint32_t)(row * AROWB + c8 * 16), g_Qh + g);
    }
    asm volatile("cp.async.commit_group;" ::: "memory");
    asm volatile("cp.async.wait_group 0;" ::: "memory");
    __syncthreads();

    uint32_t qh[4][4];
    {
        const int arow = w * 16 + (lane & 7) + ((lane >> 3) & 1) * 8;
#pragma unroll
        for (int ks = 0; ks < 4; ks++) {
            const int koff = ks * 16 + (lane >> 4) * 8;
            ldsm4(qh[ks], sb + Q_OFF + (uint32_t)(arow * AROWB + koff * 2));
        }
    }
    __syncthreads();

    float m0 = -INFINITY, m1 = -INFINITY, l0 = 0.f, l1 = 0.f;
    float o[8][4];
#pragma unroll
    for (int t = 0; t < 8; t++)
#pragma unroll
        for (int r = 0; r < 4; r++) o[t][r] = 0.f;

    const int nkb = 2 * (qt + 1);
    load_kv(sb, rowbase, headoff, 0, tid);
    asm volatile("cp.async.commit_group;" ::: "memory");
    if (1 < nkb) {
        load_kv(sb + KVSTAGE, rowbase, headoff, 64, tid);
        asm volatile("cp.async.commit_group;" ::: "memory");
    }

    int st = 0;
    for (int kt = 0; kt < nkb; kt++) {
        if (kt + 1 < nkb)
            asm volatile("cp.async.wait_group 1;" ::: "memory");
        else
            asm volatile("cp.async.wait_group 0;" ::: "memory");
        __syncthreads();
        if (kt + 2 < nkb) {
            int sn = st + 2; if (sn >= 3) sn -= 3;
            load_kv(sb + sn * KVSTAGE, rowbase, headoff, (kt + 2) * 64, tid);
            asm volatile("cp.async.commit_group;" ::: "memory");
        }

        const int k0 = kt * 64;
        const bool skip = (q0 + w * 16 + 15) < k0;
        if (!skip) {
            const uint32_t base = sb + st * KVSTAGE;
            float s[8][4];
#pragma unroll
            for (int t = 0; t < 8; t++)
#pragma unroll
                for (int r = 0; r < 4; r++) s[t][r] = 0.f;

            const int nrow = (lane & 7) + ((lane >> 4) & 1) * 8;
#pragma unroll
            for (int ks = 0; ks < 4; ks++) {
                const int koff = ks * 16 + ((lane >> 3) & 1) * 8;
#pragma unroll
                for (int p = 0; p < 4; p++) {
                    uint32_t kh[4];
                    ldsm4(kh, base + (uint32_t)((16 * p + nrow) * AROWB + koff * 2));
                    mma16816(s[2 * p],     qh[ks], &kh[0]);
                    mma16816(s[2 * p + 1], qh[ks], &kh[2]);
                }
            }

            const int row0 = q0 + w * 16 + (lane >> 2);
            if (kt >= 2 * qt) {
#pragma unroll
                for (int t = 0; t < 8; t++) {
                    int col = k0 + t * 8 + (lane & 3) * 2;
                    if (col > row0)         s[t][0] = -1e30f;
                    if (col + 1 > row0)     s[t][1] = -1e30f;
                    if (col > row0 + 8)     s[t][2] = -1e30f;
                    if (col + 1 > row0 + 8) s[t][3] = -1e30f;
                }
            }

            float mx0 = -INFINITY, mx1 = -INFINITY;
#pragma unroll
            for (int t = 0; t < 8; t++) {
                mx0 = fmaxf(mx0, fmaxf(s[t][0], s[t][1]));
                mx1 = fmaxf(mx1, fmaxf(s[t][2], s[t][3]));
            }
#pragma unroll
            for (int off = 1; off <= 2; off <<= 1) {
                mx0 = fmaxf(mx0, __shfl_xor_sync(0xffffffffu, mx0, off));
                mx1 = fmaxf(mx1, __shfl_xor_sync(0xffffffffu, mx1, off));
            }
            float mn0 = fmaxf(m0, mx0), mn1 = fmaxf(m1, mx1);
            float al0 = __expf(m0 - mn0), al1 = __expf(m1 - mn1);
            m0 = mn0; m1 = mn1;
            float rs0 = 0.f, rs1 = 0.f;
#pragma unroll
            for (int t = 0; t < 8; t++) {
                s[t][0] = __expf(s[t][0] - mn0);
                s[t][1] = __expf(s[t][1] - mn0);
                s[t][2] = __expf(s[t][2] - mn1);
                s[t][3] = __expf(s[t][3] - mn1);
                rs0 += s[t][0] + s[t][1];
                rs1 += s[t][2] + s[t][3];
            }
#pragma unroll
            for (int off = 1; off <= 2; off <<= 1) {
                rs0 += __shfl_xor_sync(0xffffffffu, rs0, off);
                rs1 += __shfl_xor_sync(0xffffffffu, rs1, off);
            }
            l0 = l0 * al0 + rs0;
            l1 = l1 * al1 + rs1;
#pragma unroll
            for (int t = 0; t < 8; t++) {
                o[t][0] *= al0; o[t][1] *= al0;
                o[t][2] *= al1; o[t][3] *= al1;
            }

            const int vrow0 = lane & 15;
            const int vcoff = (lane >> 4) * 8;
#pragma unroll
            for (int j = 0; j < 4; j++) {
                uint32_t ph[4];
                ph[0] = pack2h(s[2 * j][0], s[2 * j][1]);
                ph[1] = pack2h(s[2 * j][2], s[2 * j][3]);
                ph[2] = pack2h(s[2 * j + 1][0], s[2 * j + 1][1]);
                ph[3] = pack2h(s[2 * j + 1][2], s[2 * j + 1][3]);
#pragma unroll
                for (int p = 0; p < 4; p++) {
                    uint32_t vs[4];
                    uint32_t vo = (uint32_t)((j * 16 + vrow0) * AROWB +
                                             (16 * p + vcoff) * 2);
                    ldsm4t(vs, base + KVTILE + vo);
                    mma16816(o[2 * p],     ph, &vs[0]);
                    mma16816(o[2 * p + 1], ph, &vs[2]);
                }
            }
        }
        __syncthreads();
        if (++st == 3) st = 0;
    }

    const float inv0 = 1.f / l0, inv1 = 1.f / l1;
    const size_t row = rowbase + q0 + w * 16 + (lane >> 2);
    const size_t col = headoff + (lane & 3) * 2;
#pragma unroll
    for (int t = 0; t < 8; t++) {
        *(uint32_t*)&Oh[row * E_ + col + t * 8] =
            pack2h(o[t][0] * inv0, o[t][1] * inv0);
        *(uint32_t*)&Oh[(row + 8) * E_ + col + t * 8] =
            pack2h(o[t][2] * inv1, o[t][3] * inv1);
    }
}

// ---------------------------------------------------------------------------
extern "C" void kernel_launch(void* const* d_in, const int* in_sizes, int n_in,
                              void* d_out, int out_size) {
    const float* q_in = (const float*)d_in[0];
    const float* k_in = (const float*)d_in[1];
    const float* v_in = (const float*)d_in[2];
    const float* Wq = (const float*)d_in[3];
    const float* Wk = (const float*)d_in[4];
    const float* Wv = (const float*)d_in[5];
    const float* Wo = (const float*)d_in[6];
    float* out = (float*)d_out;

    __half* hA;
    cudaGetSymbolAddress((void**)&hA, g_hA);

    cudaFuncSetAttribute(gemm_qkv, cudaFuncAttributeMaxDynamicSharedMemorySize,
                         GEMM_SMEM);
    cudaFuncSetAttribute(gemm_o, cudaFuncAttributeMaxDynamicSharedMemorySize,
                         GEMM_SMEM);
    cudaFuncSetAttribute(flash_attn_tc,
                         cudaFuncAttributeMaxDynamicSharedMemorySize, ATTN_SMEM);

    // 0: setup (zero counters + rope sincos table)
    setup_kernel<<<(S_ * 32) / 256, 256>>>();
    // 1: all converts (4 weights + 3 activations, single fp16)
    conv_all<<<(WCHUNKS + ACHUNKS) / 256, 256>>>(Wq, Wk, Wv, Wo,
                                                 q_in, k_in, v_in);
    // 2: fused persistent Q/K/V projections w/ fused rope epilogue
    gemm_qkv<<<304, 256, GEMM_SMEM>>>();
    // 3: attention -> fp16 output into g_hA
    flash_attn_tc<<<dim3(S_ / 128, H_, B_), 256, ATTN_SMEM>>>(hA);
    // 4: persistent output projection
    gemm_o<<<304, 256, GEMM_SMEM>>>(out);
}

// round 14
// speedup vs baseline: 1.1028x; 1.1028x over previous
#include <cuda_runtime.h>
#include <cuda_fp16.h>
#include <math.h>
#include <stdint.h>

#define B_ 4
#define S_ 2048
#define E_ 1024
#define H_ 16
#define D_ 64

static const int MTOT = B_ * S_;          // 8192
#define NELEM (B_ * S_ * E_)              // 8388608
#define NW (E_ * E_)

// ---------------- scratch (__device__ globals; no allocs allowed) ----------
__device__ __half g_hA[NELEM];    // q-activation staging; later attention output
__device__ __half g_hKs[NELEM];   // k-activation staging
__device__ __half g_hT[NELEM];    // v-activation staging
__device__ __half g_W1[NW];       // Wq
__device__ __half g_W2[NW];       // Wk
__device__ __half g_W3[NW];       // Wv
__device__ __half g_W4[NW];       // Wo
__device__ __half g_Qh[NELEM];    // roped Q (1/8 folded)
__device__ __half g_Kh[NELEM];    // roped K
__device__ __half g_Vs[NELEM];    // V
__device__ float2 g_rope[S_ * 32];
__device__ unsigned int g_ctr[8];

// ---------------- helpers --------------------------------------------------
__device__ __forceinline__ uint32_t smem_u32(const void* p) {
    uint32_t a;
    asm("{ .reg .u64 t; cvta.to.shared.u64 t, %1; cvt.u32.u64 %0, t; }"
        : "=r"(a) : "l"(p));
    return a;
}
__device__ __forceinline__ void cp16(uint32_t saddr, const void* g) {
    asm volatile("cp.async.cg.shared.global [%0], [%1], 16;"
                 :: "r"(saddr), "l"(g) : "memory");
}
__device__ __forceinline__ void ldsm4(uint32_t* r, uint32_t a) {
    asm volatile("ldmatrix.sync.aligned.m8n8.x4.shared.b16 {%0,%1,%2,%3}, [%4];"
                 : "=r"(r[0]), "=r"(r[1]), "=r"(r[2]), "=r"(r[3]) : "r"(a));
}
__device__ __forceinline__ void ldsm4t(uint32_t* r, uint32_t a) {
    asm volatile("ldmatrix.sync.aligned.m8n8.x4.trans.shared.b16 {%0,%1,%2,%3}, [%4];"
                 : "=r"(r[0]), "=r"(r[1]), "=r"(r[2]), "=r"(r[3]) : "r"(a));
}
__device__ __forceinline__ void ldsm2t(uint32_t* r, uint32_t a) {
    asm volatile("ldmatrix.sync.aligned.m8n8.x2.trans.shared.b16 {%0,%1}, [%2];"
                 : "=r"(r[0]), "=r"(r[1]) : "r"(a));
}
__device__ __forceinline__ void mma16816(float* c, const uint32_t* a,
                                         const uint32_t* b) {
    asm volatile(
        "mma.sync.aligned.m16n8k16.row.col.f32.f16.f16.f32 "
        "{%0,%1,%2,%3}, {%4,%5,%6,%7}, {%8,%9}, {%0,%1,%2,%3};"
        : "+f"(c[0]), "+f"(c[1]), "+f"(c[2]), "+f"(c[3])
        : "r"(a[0]), "r"(a[1]), "r"(a[2]), "r"(a[3]), "r"(b[0]), "r"(b[1]));
}
__device__ __forceinline__ uint32_t pack2h(float x0, float x1) {
    __half2 h = __floats2half2_rn(x0, x1);
    return *(uint32_t*)&h;
}

// ---------------- setup: zero counters + rope table ------------------------
__global__ __launch_bounds__(256)
void setup_kernel() {
    int idx = blockIdx.x * 256 + threadIdx.x;   // 65536 threads
    if (idx < 8) g_ctr[idx] = 0;
    int s = idx >> 5;
    int i = idx & 31;
    float inv_freq = __expf(-(float)i * (logf(10000.0f) / 32.0f));
    float ang = (float)s * inv_freq;
    float sn, cs;
    sincosf(ang, &sn, &cs);
    g_rope[idx] = make_float2(cs, sn);
}

// ---------------- merged converts: 4 weights + 3 activations ---------------
#define WCHUNKS (4 * (NW / 8))       // 524288
#define ACHUNKS (3 * (NELEM / 8))    // 3145728
__global__ __launch_bounds__(256)
void conv_all(const float* __restrict__ W0, const float* __restrict__ W1,
              const float* __restrict__ W2, const float* __restrict__ W3,
              const float* __restrict__ Aq, const float* __restrict__ Ak,
              const float* __restrict__ Av) {
    int i = blockIdx.x * 256 + threadIdx.x;
    const float* src;
    __half* dst;
    int j;
    if (i < WCHUNKS) {
        int which = i >> 17;
        j = i & 0x1FFFF;
        src = which == 0 ? W0 : which == 1 ? W1 : which == 2 ? W2 : W3;
        dst = which == 0 ? g_W1 : which == 1 ? g_W2 : which == 2 ? g_W3 : g_W4;
    } else {
        int i2 = i - WCHUNKS;
        int which = i2 >> 20;
        j = i2 & 0xFFFFF;
        src = which == 0 ? Aq : which == 1 ? Ak : Av;
        dst = which == 0 ? g_hA : which == 1 ? g_hKs : g_hT;
    }
    float4 v0 = ((const float4*)src)[2 * j];
    float4 v1 = ((const float4*)src)[2 * j + 1];
    float f[8] = {v0.x, v0.y, v0.z, v0.w, v1.x, v1.y, v1.z, v1.w};
    uint32_t h[4];
#pragma unroll
    for (int p = 0; p < 4; p++) h[p] = pack2h(f[2 * p], f[2 * p + 1]);
    ((uint4*)dst)[j] = make_uint4(h[0], h[1], h[2], h[3]);
}

// ---------------- GEMM tile body (128x128, BK=64, 8 warps, 3-stage) -------
#define ROWB 144
#define TILEH (128 * ROWB)                 // 18432
#define STAGEH (2 * TILEH)                 // 36864
#define GEMM_SMEM (3 * STAGEH)             // 110592

// group-swap permutation for rope-fused GEMMs (involutive)
__device__ __forceinline__ int bperm(int row) {
    int g = row >> 3;
    int gs = ((g & 3) << 2) | (g >> 2);
    return (gs << 3) | (row & 7);
}

__device__ __forceinline__ void load_stage2(
    uint32_t sb, int st, const __half* __restrict__ A,
    const __half* __restrict__ Bs, int bm, int bn, int k0, int tid, int perm) {
    uint32_t s0 = sb + st * STAGEH;
#pragma unroll
    for (int p = 0; p < 4; p++) {
        int chunk = tid + p * 256;
        int row = chunk >> 3;
        int c16 = chunk & 7;
        uint32_t soff = (uint32_t)(row * ROWB + c16 * 16);
        int rB = perm ? bperm(row) : row;
        size_t ga = ((size_t)(bm + row) << 10) + k0 + c16 * 8;
        size_t gb = ((size_t)(bn + rB) << 10) + k0 + c16 * 8;
        cp16(s0 + soff,         A + ga);
        cp16(s0 + TILEH + soff, Bs + gb);
    }
}

// MODE: 0 = fp32 out, 1 = fp16 out, 2 = rope->Qh (x0.125, B-perm), 3 = rope->Kh (B-perm)
__device__ __forceinline__ void gemm_tile(
    uint32_t sb, int tid, int lane, int wid,
    const __half* __restrict__ A, const __half* __restrict__ Bs,
    float* __restrict__ C, __half* __restrict__ Ch,
    int bm, int bn, int mode) {
    const int wm = wid >> 2;
    const int wn = wid & 3;
    const int perm = (mode >= 2) ? 1 : 0;

    float acc[4][4][4];
#pragma unroll
    for (int i = 0; i < 4; i++)
#pragma unroll
        for (int j = 0; j < 4; j++)
#pragma unroll
            for (int r = 0; r < 4; r++) acc[i][j][r] = 0.f;

    load_stage2(sb, 0, A, Bs, bm, bn, 0, tid, perm);
    asm volatile("cp.async.commit_group;" ::: "memory");
    load_stage2(sb, 1, A, Bs, bm, bn, 64, tid, perm);
    asm volatile("cp.async.commit_group;" ::: "memory");

    const int NCH = E_ / 64;   // 16
    int st = 0;
    for (int c = 0; c < NCH; c++) {
        if (c + 1 < NCH)
            asm volatile("cp.async.wait_group 1;" ::: "memory");
        else
            asm volatile("cp.async.wait_group 0;" ::: "memory");
        __syncthreads();
        if (c + 2 < NCH) {
            int sn = st + 2; if (sn >= 3) sn -= 3;
            load_stage2(sb, sn, A, Bs, bm, bn, (c + 2) * 64, tid, perm);
            asm volatile("cp.async.commit_group;" ::: "memory");
        }

        const uint32_t s0 = sb + st * STAGEH;
        const uint32_t sA = s0, sB = s0 + TILEH;

#pragma unroll
        for (int ks = 0; ks < 64; ks += 16) {
            uint32_t bs[2][4];
            const int brow = wn * 32 + (lane & 7) + ((lane >> 4) & 1) * 8;
            const int bkk = ks + ((lane >> 3) & 1) * 8;
#pragma unroll
            for (int nb = 0; nb < 2; nb++)
                ldsm4(bs[nb], sB + (uint32_t)((brow + nb * 16) * ROWB + bkk * 2));
            const int arow = wm * 64 + (lane & 7) + ((lane >> 3) & 1) * 8;
            const int akk = ks + (lane >> 4) * 8;
#pragma unroll
            for (int mi = 0; mi < 4; mi++) {
                uint32_t a[4];
                ldsm4(a, sA + (uint32_t)((arow + mi * 16) * ROWB + akk * 2));
#pragma unroll
                for (int ni = 0; ni < 4; ni++)
                    mma16816(acc[mi][ni], a, &bs[ni >> 1][(ni & 1) * 2]);
            }
        }
        if (++st == 3) st = 0;
    }
    __syncthreads();   // stages dead before next tile's prologue

    const int r0 = wm * 64 + (lane >> 2);
    const int c0 = wn * 32 + (lane & 3) * 2;
    if (mode == 0) {
#pragma unroll
        for (int mi = 0; mi < 4; mi++)
#pragma unroll
            for (int ni = 0; ni < 4; ni++) {
                int row = bm + r0 + mi * 16;
                int col = bn + c0 + ni * 8;
                *(float2*)&C[(size_t)row * E_ + col] =
                    make_float2(acc[mi][ni][0], acc[mi][ni][1]);
                *(float2*)&C[(size_t)(row + 8) * E_ + col] =
                    make_float2(acc[mi][ni][2], acc[mi][ni][3]);
            }
    } else if (mode == 1) {
#pragma unroll
        for (int mi = 0; mi < 4; mi++)
#pragma unroll
            for (int ni = 0; ni < 4; ni++) {
                int row = bm + r0 + mi * 16;
                int col = bn + c0 + ni * 8;
                *(uint32_t*)&Ch[(size_t)row * E_ + col] =
                    pack2h(acc[mi][ni][0], acc[mi][ni][1]);
                *(uint32_t*)&Ch[(size_t)(row + 8) * E_ + col] =
                    pack2h(acc[mi][ni][2], acc[mi][ni][3]);
            }
    } else {
        // register-local rope: with B-perm, ni pairs (0,1) = head0 (i, i+32),
        // (2,3) = head1 (i, i+32), i = wn*8 + (lane&3)*2
        const float sc = (mode == 2) ? 0.125f : 1.0f;
        const int ip = wn * 8 + (lane & 3) * 2;
#pragma unroll
        for (int mi = 0; mi < 4; mi++) {
#pragma unroll
            for (int hf = 0; hf < 2; hf++) {
                int row = bm + r0 + mi * 16 + hf * 8;
                const float2* tab = g_rope + (size_t)(row & (S_ - 1)) * 32 + ip;
                float2 t0 = tab[0], t1 = tab[1];
                size_t gb = (size_t)row * E_ + bn;
                float x1a = acc[mi][0][hf * 2], x1b = acc[mi][0][hf * 2 + 1];
                float x2a = acc[mi][1][hf * 2], x2b = acc[mi][1][hf * 2 + 1];
                *(uint32_t*)&Ch[gb + ip] =
                    pack2h((x1a * t0.x - x2a * t0.y) * sc,
                           (x1b * t1.x - x2b * t1.y) * sc);
                *(uint32_t*)&Ch[gb + ip + 32] =
                    pack2h((x2a * t0.x + x1a * t0.y) * sc,
                           (x2b * t1.x + x1b * t1.y) * sc);
                x1a = acc[mi][2][hf * 2]; x1b = acc[mi][2][hf * 2 + 1];
                x2a = acc[mi][3][hf * 2]; x2b = acc[mi][3][hf * 2 + 1];
                *(uint32_t*)&Ch[gb + 64 + ip] =
                    pack2h((x1a * t0.x - x2a * t0.y) * sc,
                           (x1b * t1.x - x2b * t1.y) * sc);
                *(uint32_t*)&Ch[gb + 64 + ip + 32] =
                    pack2h((x2a * t0.x + x1a * t0.y) * sc,
                           (x2b * t1.x + x1b * t1.y) * sc);
            }
        }
    }
}

// Persistent fused Q/K/V projections: 1536 tiles on g_ctr[0].
__global__ __launch_bounds__(256, 2)
void gemm_qkv() {
    extern __shared__ char smem[];
    const uint32_t sb = smem_u32(smem);
    const int tid = threadIdx.x;
    const int lane = tid & 31;
    const int wid = tid >> 5;
    __shared__ unsigned s_t;

    for (;;) {
        if (tid == 0) s_t = atomicAdd(&g_ctr[0], 1u);
        __syncthreads();
        unsigned t = s_t;
        __syncthreads();
        if (t >= 1536u) return;
        int which = t >> 9;
        int rem = t & 511;
        int bm = (rem >> 3) * 128, bn = (rem & 7) * 128;
        if (which == 0)
            gemm_tile(sb, tid, lane, wid, g_hA, g_W1, nullptr, g_Qh, bm, bn, 2);
        else if (which == 1)
            gemm_tile(sb, tid, lane, wid, g_hKs, g_W2, nullptr, g_Kh, bm, bn, 3);
        else
            gemm_tile(sb, tid, lane, wid, g_hT, g_W3, nullptr, g_Vs, bm, bn, 1);
    }
}

// Persistent output projection: 512 tiles on g_ctr[1].
__global__ __launch_bounds__(256, 2)
void gemm_o(float* __restrict__ out) {
    extern __shared__ char smem[];
    const uint32_t sb = smem_u32(smem);
    const int tid = threadIdx.x;
    const int lane = tid & 31;
    const int wid = tid >> 5;
    __shared__ unsigned s_t;

    for (;;) {
        if (tid == 0) s_t = atomicAdd(&g_ctr[1], 1u);
        __syncthreads();
        unsigned t = s_t;
        __syncthreads();
        if (t >= 512u) return;
        int bm = (t >> 3) * 128, bn = (t & 7) * 128;
        gemm_tile(sb, tid, lane, wid, g_hA, g_W4, out, nullptr, bm, bn, 0);
    }
}

// ---------------- tensor-core causal flash attention ----------------------
// KV stage: {Ks, Vs} 64 rows x 144B; 3-stage ring; Q tile above.
// V rows' padding halves (cols 64-71) carry a ones column -> l via MMA.
#define AROWB 144
#define KVTILE (64 * AROWB)                 // 9216
#define KVSTAGE (2 * KVTILE)                // 18432
#define Q_OFF (3 * KVSTAGE)                 // 55296
#define ATTN_SMEM (Q_OFF + 128 * AROWB)     // 73728

__device__ __forceinline__ void load_kv(
    uint32_t sb, size_t rowbase, size_t headoff, int k0, int tid) {
#pragma unroll
    for (int p = 0; p < 2; p++) {
        int chunk = tid + p * 256;
        int row = chunk >> 3;
        int c8 = chunk & 7;
        size_t g = (rowbase + k0 + row) * E_ + headoff + c8 * 8;
        uint32_t so = (uint32_t)(row * AROWB + c8 * 16);
        cp16(sb + so,          g_Kh + g);
        cp16(sb + KVTILE + so, g_Vs + g);
    }
}

__global__ __launch_bounds__(256, 2)
void flash_attn_tc(__half* __restrict__ Oh) {
    extern __shared__ char smem[];
    const uint32_t sb = smem_u32(smem);
    const int tid = threadIdx.x;
    const int lane = tid & 31;
    const int w = tid >> 5;
    const int qt = gridDim.x - 1 - blockIdx.x;
    const int h = blockIdx.y;
    const int b = blockIdx.z;
    const int q0 = qt * 128;
    const size_t rowbase = (size_t)(b * S_);
    const size_t headoff = (size_t)h * D_;

    // init ones column in the padding halves of all 3 V-stage tiles
    if (tid < 192) {
        int stg = tid / 64, row = tid % 64;
        __half ones[8] = {__float2half(1.f), __float2half(0.f), __float2half(0.f),
                          __float2half(0.f), __float2half(0.f), __float2half(0.f),
                          __float2half(0.f), __float2half(0.f)};
        *(uint4*)(smem + stg * KVSTAGE + KVTILE + row * AROWB + 128) =
            *(uint4*)ones;
    }

    // stage Q
#pragma unroll
    for (int p = 0; p < 4; p++) {
        int chunk = tid + p * 256;
        int row = chunk >> 3;
        int c8 = chunk & 7;
        size_t g = (rowbase + q0 + row) * E_ + headoff + c8 * 8;
        cp16(sb + Q_OFF + (uint32_t)(row * AROWB + c8 * 16), g_Qh + g);
    }
    asm volatile("cp.async.commit_group;" ::: "memory");
    asm volatile("cp.async.wait_group 0;" ::: "memory");
    __syncthreads();

    uint32_t qh[4][4];
    {
        const int arow = w * 16 + (lane & 7) + ((lane >> 3) & 1) * 8;
#pragma unroll
        for (int ks = 0; ks < 4; ks++) {
            const int koff = ks * 16 + (lane >> 4) * 8;
            ldsm4(qh[ks], sb + Q_OFF + (uint32_t)(arow * AROWB + koff * 2));
        }
    }
    __syncthreads();

    float m0 = -INFINITY, m1 = -INFINITY;
    float o[8][4], lacc[4];
#pragma unroll
    for (int t = 0; t < 8; t++)
#pragma unroll
        for (int r = 0; r < 4; r++) o[t][r] = 0.f;
#pragma unroll
    for (int r = 0; r < 4; r++) lacc[r] = 0.f;

    const int nkb = 2 * (qt + 1);
    load_kv(sb, rowbase, headoff, 0, tid);
    asm volatile("cp.async.commit_group;" ::: "memory");
    if (1 < nkb) {
        load_kv(sb + KVSTAGE, rowbase, headoff, 64, tid);
        asm volatile("cp.async.commit_group;" ::: "memory");
    }

    int st = 0;
    for (int kt = 0; kt < nkb; kt++) {
        if (kt + 1 < nkb)
            asm volatile("cp.async.wait_group 1;" ::: "memory");
        else
            asm volatile("cp.async.wait_group 0;" ::: "memory");
        __syncthreads();
        if (kt + 2 < nkb) {
            int sn = st + 2; if (sn >= 3) sn -= 3;
            load_kv(sb + sn * KVSTAGE, rowbase, headoff, (kt + 2) * 64, tid);
            asm volatile("cp.async.commit_group;" ::: "memory");
        }

        const int k0 = kt * 64;
        const bool skip = (q0 + w * 16 + 15) < k0;
        if (!skip) {
            const uint32_t base = sb + st * KVSTAGE;
            float s[8][4];
#pragma unroll
            for (int t = 0; t < 8; t++)
#pragma unroll
                for (int r = 0; r < 4; r++) s[t][r] = 0.f;

            const int nrow = (lane & 7) + ((lane >> 4) & 1) * 8;
#pragma unroll
            for (int ks = 0; ks < 4; ks++) {
                const int koff = ks * 16 + ((lane >> 3) & 1) * 8;
#pragma unroll
                for (int p = 0; p < 4; p++) {
                    uint32_t kh[4];
                    ldsm4(kh, base + (uint32_t)((16 * p + nrow) * AROWB + koff * 2));
                    mma16816(s[2 * p],     qh[ks], &kh[0]);
                    mma16816(s[2 * p + 1], qh[ks], &kh[2]);
                }
            }

            const int row0 = q0 + w * 16 + (lane >> 2);
            if (kt >= 2 * qt) {
#pragma unroll
                for (int t = 0; t < 8; t++) {
                    int col = k0 + t * 8 + (lane & 3) * 2;
                    if (col > row0)         s[t][0] = -1e30f;
                    if (col + 1 > row0)     s[t][1] = -1e30f;
                    if (col > row0 + 8)     s[t][2] = -1e30f;
                    if (col + 1 > row0 + 8) s[t][3] = -1e30f;
                }
            }

            float mx0 = -INFINITY, mx1 = -INFINITY;
#pragma unroll
            for (int t = 0; t < 8; t++) {
                mx0 = fmaxf(mx0, fmaxf(s[t][0], s[t][1]));
                mx1 = fmaxf(mx1, fmaxf(s[t][2], s[t][3]));
            }
#pragma unroll
            for (int off = 1; off <= 2; off <<= 1) {
                mx0 = fmaxf(mx0, __shfl_xor_sync(0xffffffffu, mx0, off));
                mx1 = fmaxf(mx1, __shfl_xor_sync(0xffffffffu, mx1, off));
            }
            float mn0 = fmaxf(m0, mx0), mn1 = fmaxf(m1, mx1);
            float al0 = __expf(m0 - mn0), al1 = __expf(m1 - mn1);
            m0 = mn0; m1 = mn1;
#pragma unroll
            for (int t = 0; t < 8; t++) {
                s[t][0] = __expf(s[t][0] - mn0);
                s[t][1] = __expf(s[t][1] - mn0);
                s[t][2] = __expf(s[t][2] - mn1);
                s[t][3] = __expf(s[t][3] - mn1);
            }
#pragma unroll
            for (int t = 0; t < 8; t++) {
                o[t][0] *= al0; o[t][1] *= al0;
                o[t][2] *= al1; o[t][3] *= al1;
            }
            lacc[0] *= al0; lacc[1] *= al0;
            lacc[2] *= al1; lacc[3] *= al1;

            const int vrow0 = lane & 15;
            const int vcoff = (lane >> 4) * 8;
#pragma unroll
            for (int j = 0; j < 4; j++) {
                uint32_t ph[4];
                ph[0] = pack2h(s[2 * j][0], s[2 * j][1]);
                ph[1] = pack2h(s[2 * j][2], s[2 * j][3]);
                ph[2] = pack2h(s[2 * j + 1][0], s[2 * j + 1][1]);
                ph[3] = pack2h(s[2 * j + 1][2], s[2 * j + 1][3]);
#pragma unroll
                for (int p = 0; p < 4; p++) {
                    uint32_t vs[4];
                    uint32_t vo = (uint32_t)((j * 16 + vrow0) * AROWB +
                                             (16 * p + vcoff) * 2);
                    ldsm4t(vs, base + KVTILE + vo);
                    mma16816(o[2 * p],     ph, &vs[0]);
                    mma16816(o[2 * p + 1], ph, &vs[2]);
                }
                // l += P @ ones (padding col 64)
                uint32_t vone[2];
                ldsm2t(vone, base + KVTILE +
                       (uint32_t)((j * 16 + (lane & 15)) * AROWB + 128));
                mma16816(lacc, ph, vone);
            }
        }
        __syncthreads();
        if (++st == 3) st = 0;
    }

    // l broadcast: col 64 lives in lanes with (lane&3)==0
    float l0 = __shfl_sync(0xffffffffu, lacc[0], lane & 28);
    float l1 = __shfl_sync(0xffffffffu, lacc[2], lane & 28);
    const float inv0 = 1.f / l0, inv1 = 1.f / l1;
    const size_t row = rowbase + q0 + w * 16 + (lane >> 2);
    const size_t col = headoff + (lane & 3) * 2;
#pragma unroll
    for (int t = 0; t < 8; t++) {
        *(uint32_t*)&Oh[row * E_ + col + t * 8] =
            pack2h(o[t][0] * inv0, o[t][1] * inv0);
        *(uint32_t*)&Oh[(row + 8) * E_ + col + t * 8] =
            pack2h(o[t][2] * inv1, o[t][3] * inv1);
    }
}

// ---------------------------------------------------------------------------
extern "C" void kernel_launch(void* const* d_in, const int* in_sizes, int n_in,
                              void* d_out, int out_size) {
    const float* q_in = (const float*)d_in[0];
    const float* k_in = (const float*)d_in[1];
    const float* v_in = (const float*)d_in[2];
    const float* Wq = (const float*)d_in[3];
    const float* Wk = (const float*)d_in[4];
    const float* Wv = (const float*)d_in[5];
    const float* Wo = (const float*)d_in[6];
    float* out = (float*)d_out;

    __half* hA;
    cudaGetSymbolAddress((void**)&hA, g_hA);

    cudaFuncSetAttribute(gemm_qkv, cudaFuncAttributeMaxDynamicSharedMemorySize,
                         GEMM_SMEM);
    cudaFuncSetAttribute(gemm_o, cudaFuncAttributeMaxDynamicSharedMemorySize,
                         GEMM_SMEM);
    cudaFuncSetAttribute(flash_attn_tc,
                         cudaFuncAttributeMaxDynamicSharedMemorySize, ATTN_SMEM);

    // 0: setup (counters + rope table)
    setup_kernel<<<(S_ * 32) / 256, 256>>>();
    // 1: all converts (weights + activations, single fp16)
    conv_all<<<(WCHUNKS + ACHUNKS) / 256, 256>>>(Wq, Wk, Wv, Wo,
                                                 q_in, k_in, v_in);
    // 2: fused persistent Q/K/V projections with register-local rope
    gemm_qkv<<<304, 256, GEMM_SMEM>>>();
    // 3: attention (l via tensor-core ones column)
    flash_attn_tc<<<dim3(S_ / 128, H_, B_), 256, ATTN_SMEM>>>(hA);
    // 4: persistent output projection
    gemm_o<<<304, 256, GEMM_SMEM>>>(out);
}

// round 16
// speedup vs baseline: 1.1220x; 1.0174x over previous
#include <cuda_runtime.h>
#include <cuda_fp16.h>
#include <math.h>
#include <stdint.h>

#define B_ 4
#define S_ 2048
#define E_ 1024
#define H_ 16
#define D_ 64

static const int MTOT = B_ * S_;          // 8192
#define NELEM (B_ * S_ * E_)              // 8388608
#define NW (E_ * E_)

// ---------------- scratch (__device__ globals; no allocs allowed) ----------
__device__ __half g_hA[NELEM];    // q-activation staging; later attention output
__device__ __half g_hKs[NELEM];   // k-activation staging
__device__ __half g_hT[NELEM];    // v-activation staging
__device__ __half g_W1[NW];       // Wq
__device__ __half g_W2[NW];       // Wk
__device__ __half g_W3[NW];       // Wv
__device__ __half g_W4[NW];       // Wo
__device__ __half g_Qh[NELEM];    // roped Q (log2e/8 folded)
__device__ __half g_Kh[NELEM];    // roped K
__device__ __half g_Vs[NELEM];    // V
__device__ float2 g_rope[S_ * 32];
__device__ unsigned int g_ctr[8];

// ---------------- helpers --------------------------------------------------
__device__ __forceinline__ uint32_t smem_u32(const void* p) {
    uint32_t a;
    asm("{ .reg .u64 t; cvta.to.shared.u64 t, %1; cvt.u32.u64 %0, t; }"
        : "=r"(a) : "l"(p));
    return a;
}
__device__ __forceinline__ void cp16(uint32_t saddr, const void* g) {
    asm volatile("cp.async.cg.shared.global [%0], [%1], 16;"
                 :: "r"(saddr), "l"(g) : "memory");
}
__device__ __forceinline__ void ldsm4(uint32_t* r, uint32_t a) {
    asm volatile("ldmatrix.sync.aligned.m8n8.x4.shared.b16 {%0,%1,%2,%3}, [%4];"
                 : "=r"(r[0]), "=r"(r[1]), "=r"(r[2]), "=r"(r[3]) : "r"(a));
}
__device__ __forceinline__ void ldsm4t(uint32_t* r, uint32_t a) {
    asm volatile("ldmatrix.sync.aligned.m8n8.x4.trans.shared.b16 {%0,%1,%2,%3}, [%4];"
                 : "=r"(r[0]), "=r"(r[1]), "=r"(r[2]), "=r"(r[3]) : "r"(a));
}
__device__ __forceinline__ void ldsm2t(uint32_t* r, uint32_t a) {
    asm volatile("ldmatrix.sync.aligned.m8n8.x2.trans.shared.b16 {%0,%1}, [%2];"
                 : "=r"(r[0]), "=r"(r[1]) : "r"(a));
}
__device__ __forceinline__ void mma16816(float* c, const uint32_t* a,
                                         const uint32_t* b) {
    asm volatile(
        "mma.sync.aligned.m16n8k16.row.col.f32.f16.f16.f32 "
        "{%0,%1,%2,%3}, {%4,%5,%6,%7}, {%8,%9}, {%0,%1,%2,%3};"
        : "+f"(c[0]), "+f"(c[1]), "+f"(c[2]), "+f"(c[3])
        : "r"(a[0]), "r"(a[1]), "r"(a[2]), "r"(a[3]), "r"(b[0]), "r"(b[1]));
}
__device__ __forceinline__ uint32_t pack2h(float x0, float x1) {
    __half2 h = __floats2half2_rn(x0, x1);
    return *(uint32_t*)&h;
}
__device__ __forceinline__ uint32_t h2ex2(uint32_t x) {
    uint32_t r;
    asm("ex2.approx.f16x2 %0, %1;" : "=r"(r) : "r"(x));
    return r;
}

// ---------------- setup: zero counters + rope table ------------------------
__global__ __launch_bounds__(256)
void setup_kernel() {
    int idx = blockIdx.x * 256 + threadIdx.x;   // 65536 threads
    if (idx < 8) g_ctr[idx] = 0;
    int s = idx >> 5;
    int i = idx & 31;
    float inv_freq = __expf(-(float)i * (logf(10000.0f) / 32.0f));
    float ang = (float)s * inv_freq;
    float sn, cs;
    sincosf(ang, &sn, &cs);
    g_rope[idx] = make_float2(cs, sn);
}

// ---------------- merged converts (16 floats / thread) ---------------------
#define WCH16 (4 * (NW / 16))        // 262144
#define ACH16 (3 * (NELEM / 16))     // 1572864
__global__ __launch_bounds__(256)
void conv_all(const float* __restrict__ W0, const float* __restrict__ W1,
              const float* __restrict__ W2, const float* __restrict__ W3,
              const float* __restrict__ Aq, const float* __restrict__ Ak,
              const float* __restrict__ Av) {
    int i = blockIdx.x * 256 + threadIdx.x;
    const float* src;
    __half* dst;
    int j;
    if (i < WCH16) {
        int which = i >> 16;
        j = i & 0xFFFF;
        src = which == 0 ? W0 : which == 1 ? W1 : which == 2 ? W2 : W3;
        dst = which == 0 ? g_W1 : which == 1 ? g_W2 : which == 2 ? g_W3 : g_W4;
    } else {
        int i2 = i - WCH16;
        int which = i2 >> 19;
        j = i2 & 0x7FFFF;
        src = which == 0 ? Aq : which == 1 ? Ak : Av;
        dst = which == 0 ? g_hA : which == 1 ? g_hKs : g_hT;
    }
#pragma unroll
    for (int q = 0; q < 2; q++) {
        float4 v0 = ((const float4*)src)[4 * j + 2 * q];
        float4 v1 = ((const float4*)src)[4 * j + 2 * q + 1];
        float f[8] = {v0.x, v0.y, v0.z, v0.w, v1.x, v1.y, v1.z, v1.w};
        uint32_t h[4];
#pragma unroll
        for (int p = 0; p < 4; p++) h[p] = pack2h(f[2 * p], f[2 * p + 1]);
        ((uint4*)dst)[2 * j + q] = make_uint4(h[0], h[1], h[2], h[3]);
    }
}

// ---------------- GEMM tile body (128x128, BK=64, 8 warps, 3-stage) -------
#define ROWB 144
#define TILEH (128 * ROWB)                 // 18432
#define STAGEH (2 * TILEH)                 // 36864
#define GEMM_SMEM (3 * STAGEH)             // 110592

// group-swap permutation for rope-fused GEMMs (involutive)
__device__ __forceinline__ int bperm(int row) {
    int g = row >> 3;
    int gs = ((g & 3) << 2) | (g >> 2);
    return (gs << 3) | (row & 7);
}

__device__ __forceinline__ void load_stage2(
    uint32_t sb, int st, const __half* __restrict__ A,
    const __half* __restrict__ Bs, int bm, int bn, int k0, int tid, int perm) {
    uint32_t s0 = sb + st * STAGEH;
#pragma unroll
    for (int p = 0; p < 4; p++) {
        int chunk = tid + p * 256;
        int row = chunk >> 3;
        int c16 = chunk & 7;
        uint32_t soff = (uint32_t)(row * ROWB + c16 * 16);
        int rB = perm ? bperm(row) : row;
        size_t ga = ((size_t)(bm + row) << 10) + k0 + c16 * 8;
        size_t gb = ((size_t)(bn + rB) << 10) + k0 + c16 * 8;
        cp16(s0 + soff,         A + ga);
        cp16(s0 + TILEH + soff, Bs + gb);
    }
}

// MODE: 0 = fp32 out, 1 = fp16 out, 2 = rope->Qh (x log2e/8, B-perm), 3 = rope->Kh (B-perm)
__device__ __forceinline__ void gemm_tile(
    uint32_t sb, int tid, int lane, int wid,
    const __half* __restrict__ A, const __half* __restrict__ Bs,
    float* __restrict__ C, __half* __restrict__ Ch,
    int bm, int bn, int mode) {
    const int wm = wid >> 2;
    const int wn = wid & 3;
    const int perm = (mode >= 2) ? 1 : 0;

    float acc[4][4][4];
#pragma unroll
    for (int i = 0; i < 4; i++)
#pragma unroll
        for (int j = 0; j < 4; j++)
#pragma unroll
            for (int r = 0; r < 4; r++) acc[i][j][r] = 0.f;

    load_stage2(sb, 0, A, Bs, bm, bn, 0, tid, perm);
    asm volatile("cp.async.commit_group;" ::: "memory");
    load_stage2(sb, 1, A, Bs, bm, bn, 64, tid, perm);
    asm volatile("cp.async.commit_group;" ::: "memory");

    const int NCH = E_ / 64;   // 16
    int st = 0;
    for (int c = 0; c < NCH; c++) {
        if (c + 1 < NCH)
            asm volatile("cp.async.wait_group 1;" ::: "memory");
        else
            asm volatile("cp.async.wait_group 0;" ::: "memory");
        __syncthreads();
        if (c + 2 < NCH) {
            int sn = st + 2; if (sn >= 3) sn -= 3;
            load_stage2(sb, sn, A, Bs, bm, bn, (c + 2) * 64, tid, perm);
            asm volatile("cp.async.commit_group;" ::: "memory");
        }

        const uint32_t s0 = sb + st * STAGEH;
        const uint32_t sA = s0, sB = s0 + TILEH;

#pragma unroll
        for (int ks = 0; ks < 64; ks += 16) {
            uint32_t bs[2][4];
            const int brow = wn * 32 + (lane & 7) + ((lane >> 4) & 1) * 8;
            const int bkk = ks + ((lane >> 3) & 1) * 8;
#pragma unroll
            for (int nb = 0; nb < 2; nb++)
                ldsm4(bs[nb], sB + (uint32_t)((brow + nb * 16) * ROWB + bkk * 2));
            const int arow = wm * 64 + (lane & 7) + ((lane >> 3) & 1) * 8;
            const int akk = ks + (lane >> 4) * 8;
#pragma unroll
            for (int mi = 0; mi < 4; mi++) {
                uint32_t a[4];
                ldsm4(a, sA + (uint32_t)((arow + mi * 16) * ROWB + akk * 2));
#pragma unroll
                for (int ni = 0; ni < 4; ni++)
                    mma16816(acc[mi][ni], a, &bs[ni >> 1][(ni & 1) * 2]);
            }
        }
        if (++st == 3) st = 0;
    }
    __syncthreads();   // stages dead before next tile's prologue

    const int r0 = wm * 64 + (lane >> 2);
    const int c0 = wn * 32 + (lane & 3) * 2;
    if (mode == 0) {
#pragma unroll
        for (int mi = 0; mi < 4; mi++)
#pragma unroll
            for (int ni = 0; ni < 4; ni++) {
                int row = bm + r0 + mi * 16;
                int col = bn + c0 + ni * 8;
                *(float2*)&C[(size_t)row * E_ + col] =
                    make_float2(acc[mi][ni][0], acc[mi][ni][1]);
                *(float2*)&C[(size_t)(row + 8) * E_ + col] =
                    make_float2(acc[mi][ni][2], acc[mi][ni][3]);
            }
    } else if (mode == 1) {
#pragma unroll
        for (int mi = 0; mi < 4; mi++)
#pragma unroll
            for (int ni = 0; ni < 4; ni++) {
                int row = bm + r0 + mi * 16;
                int col = bn + c0 + ni * 8;
                *(uint32_t*)&Ch[(size_t)row * E_ + col] =
                    pack2h(acc[mi][ni][0], acc[mi][ni][1]);
                *(uint32_t*)&Ch[(size_t)(row + 8) * E_ + col] =
                    pack2h(acc[mi][ni][2], acc[mi][ni][3]);
            }
    } else {
        // register-local rope: ni pairs (0,1) = head0 (i, i+32),
        // (2,3) = head1 (i, i+32), i = wn*8 + (lane&3)*2
        // mode 2 (Q): fold softmax 1/8 AND log2(e) for log2-domain softmax
        const float sc = (mode == 2) ? 0.125f * 1.44269504088896f : 1.0f;
        const int ip = wn * 8 + (lane & 3) * 2;
#pragma unroll
        for (int mi = 0; mi < 4; mi++) {
#pragma unroll
            for (int hf = 0; hf < 2; hf++) {
                int row = bm + r0 + mi * 16 + hf * 8;
                const float2* tab = g_rope + (size_t)(row & (S_ - 1)) * 32 + ip;
                float2 t0 = tab[0], t1 = tab[1];
                size_t gb = (size_t)row * E_ + bn;
                float x1a = acc[mi][0][hf * 2], x1b = acc[mi][0][hf * 2 + 1];
                float x2a = acc[mi][1][hf * 2], x2b = acc[mi][1][hf * 2 + 1];
                *(uint32_t*)&Ch[gb + ip] =
                    pack2h((x1a * t0.x - x2a * t0.y) * sc,
                           (x1b * t1.x - x2b * t1.y) * sc);
                *(uint32_t*)&Ch[gb + ip + 32] =
                    pack2h((x2a * t0.x + x1a * t0.y) * sc,
                           (x2b * t1.x + x1b * t1.y) * sc);
                x1a = acc[mi][2][hf * 2]; x1b = acc[mi][2][hf * 2 + 1];
                x2a = acc[mi][3][hf * 2]; x2b = acc[mi][3][hf * 2 + 1];
                *(uint32_t*)&Ch[gb + 64 + ip] =
                    pack2h((x1a * t0.x - x2a * t0.y) * sc,
                           (x1b * t1.x - x2b * t1.y) * sc);
                *(uint32_t*)&Ch[gb + 64 + ip + 32] =
                    pack2h((x2a * t0.x + x1a * t0.y) * sc,
                           (x2b * t1.x + x1b * t1.y) * sc);
            }
        }
    }
}

// Persistent fused Q/K/V projections: 1536 tiles on g_ctr[0].
__global__ __launch_bounds__(256, 2)
void gemm_qkv() {
    extern __shared__ char smem[];
    const uint32_t sb = smem_u32(smem);
    const int tid = threadIdx.x;
    const int lane = tid & 31;
    const int wid = tid >> 5;
    __shared__ unsigned s_t;

    for (;;) {
        if (tid == 0) s_t = atomicAdd(&g_ctr[0], 1u);
        __syncthreads();
        unsigned t = s_t;
        __syncthreads();
        if (t >= 1536u) return;
        int which = t >> 9;
        int rem = t & 511;
        int bm = (rem >> 3) * 128, bn = (rem & 7) * 128;
        if (which == 0)
            gemm_tile(sb, tid, lane, wid, g_hA, g_W1, nullptr, g_Qh, bm, bn, 2);
        else if (which == 1)
            gemm_tile(sb, tid, lane, wid, g_hKs, g_W2, nullptr, g_Kh, bm, bn, 3);
        else
            gemm_tile(sb, tid, lane, wid, g_hT, g_W3, nullptr, g_Vs, bm, bn, 1);
    }
}

// Persistent output projection: 512 tiles on g_ctr[1].
__global__ __launch_bounds__(256, 2)
void gemm_o(float* __restrict__ out) {
    extern __shared__ char smem[];
    const uint32_t sb = smem_u32(smem);
    const int tid = threadIdx.x;
    const int lane = tid & 31;
    const int wid = tid >> 5;
    __shared__ unsigned s_t;

    for (;;) {
        if (tid == 0) s_t = atomicAdd(&g_ctr[1], 1u);
        __syncthreads();
        unsigned t = s_t;
        __syncthreads();
        if (t >= 512u) return;
        int bm = (t >> 3) * 128, bn = (t & 7) * 128;
        gemm_tile(sb, tid, lane, wid, g_hA, g_W4, out, nullptr, bm, bn, 0);
    }
}

// ---------------- tensor-core causal flash attention ----------------------
// Log2-domain softmax (log2e folded into Q); exp via ex2.approx.f16x2.
// KV stage: {Ks, Vs} 64 rows x 144B; 3-stage ring; Q tile above.
// V rows' padding halves carry a ones column -> l via MMA.
#define AROWB 144
#define KVTILE (64 * AROWB)                 // 9216
#define KVSTAGE (2 * KVTILE)                // 18432
#define Q_OFF (3 * KVSTAGE)                 // 55296
#define ATTN_SMEM (Q_OFF + 128 * AROWB)     // 73728

__device__ __forceinline__ void load_kv(
    uint32_t sb, size_t rowbase, size_t headoff, int k0, int tid) {
#pragma unroll
    for (int p = 0; p < 2; p++) {
        int chunk = tid + p * 256;
        int row = chunk >> 3;
        int c8 = chunk & 7;
        size_t g = (rowbase + k0 + row) * E_ + headoff + c8 * 8;
        uint32_t so = (uint32_t)(row * AROWB + c8 * 16);
        cp16(sb + so,          g_Kh + g);
        cp16(sb + KVTILE + so, g_Vs + g);
    }
}

__global__ __launch_bounds__(256, 2)
void flash_attn_tc(__half* __restrict__ Oh) {
    extern __shared__ char smem[];
    const uint32_t sb = smem_u32(smem);
    const int tid = threadIdx.x;
    const int lane = tid & 31;
    const int w = tid >> 5;
    const int qt = gridDim.x - 1 - blockIdx.x;
    const int h = blockIdx.y;
    const int b = blockIdx.z;
    const int q0 = qt * 128;
    const size_t rowbase = (size_t)(b * S_);
    const size_t headoff = (size_t)h * D_;

    // init ones column in the padding halves of all 3 V-stage tiles
    if (tid < 192) {
        int stg = tid / 64, row = tid % 64;
        __half ones[8] = {__float2half(1.f), __float2half(0.f), __float2half(0.f),
                          __float2half(0.f), __float2half(0.f), __float2half(0.f),
                          __float2half(0.f), __float2half(0.f)};
        *(uint4*)(smem + stg * KVSTAGE + KVTILE + row * AROWB + 128) =
            *(uint4*)ones;
    }

    // stage Q
#pragma unroll
    for (int p = 0; p < 4; p++) {
        int chunk = tid + p * 256;
        int row = chunk >> 3;
        int c8 = chunk & 7;
        size_t g = (rowbase + q0 + row) * E_ + headoff + c8 * 8;
        cp16(sb + Q_OFF + (uint32_t)(row * AROWB + c8 * 16), g_Qh + g);
    }
    asm volatile("cp.async.commit_group;" ::: "memory");
    asm volatile("cp.async.wait_group 0;" ::: "memory");
    __syncthreads();

    uint32_t qh[4][4];
    {
        const int arow = w * 16 + (lane & 7) + ((lane >> 3) & 1) * 8;
#pragma unroll
        for (int ks = 0; ks < 4; ks++) {
            const int koff = ks * 16 + (lane >> 4) * 8;
            ldsm4(qh[ks], sb + Q_OFF + (uint32_t)(arow * AROWB + koff * 2));
        }
    }
    __syncthreads();

    float m0 = -INFINITY, m1 = -INFINITY;
    float o[8][4], lacc[4];
#pragma unroll
    for (int t = 0; t < 8; t++)
#pragma unroll
        for (int r = 0; r < 4; r++) o[t][r] = 0.f;
#pragma unroll
    for (int r = 0; r < 4; r++) lacc[r] = 0.f;

    const int nkb = 2 * (qt + 1);
    load_kv(sb, rowbase, headoff, 0, tid);
    asm volatile("cp.async.commit_group;" ::: "memory");
    if (1 < nkb) {
        load_kv(sb + KVSTAGE, rowbase, headoff, 64, tid);
        asm volatile("cp.async.commit_group;" ::: "memory");
    }

    int st = 0;
    for (int kt = 0; kt < nkb; kt++) {
        if (kt + 1 < nkb)
            asm volatile("cp.async.wait_group 1;" ::: "memory");
        else
            asm volatile("cp.async.wait_group 0;" ::: "memory");
        __syncthreads();
        if (kt + 2 < nkb) {
            int sn = st + 2; if (sn >= 3) sn -= 3;
            load_kv(sb + sn * KVSTAGE, rowbase, headoff, (kt + 2) * 64, tid);
            asm volatile("cp.async.commit_group;" ::: "memory");
        }

        const int k0 = kt * 64;
        const bool skip = (q0 + w * 16 + 15) < k0;
        if (!skip) {
            const uint32_t base = sb + st * KVSTAGE;
            float s[8][4];
#pragma unroll
            for (int t = 0; t < 8; t++)
#pragma unroll
                for (int r = 0; r < 4; r++) s[t][r] = 0.f;

            const int nrow = (lane & 7) + ((lane >> 4) & 1) * 8;
#pragma unroll
            for (int ks = 0; ks < 4; ks++) {
                const int koff = ks * 16 + ((lane >> 3) & 1) * 8;
#pragma unroll
                for (int p = 0; p < 4; p++) {
                    uint32_t kh[4];
                    ldsm4(kh, base + (uint32_t)((16 * p + nrow) * AROWB + koff * 2));
                    mma16816(s[2 * p],     qh[ks], &kh[0]);
                    mma16816(s[2 * p + 1], qh[ks], &kh[2]);
                }
            }

            const int row0 = q0 + w * 16 + (lane >> 2);
            if (kt >= 2 * qt) {
#pragma unroll
                for (int t = 0; t < 8; t++) {
                    int col = k0 + t * 8 + (lane & 3) * 2;
                    if (col > row0)         s[t][0] = -1e30f;
                    if (col + 1 > row0)     s[t][1] = -1e30f;
                    if (col > row0 + 8)     s[t][2] = -1e30f;
                    if (col + 1 > row0 + 8) s[t][3] = -1e30f;
                }
            }

            float mx0 = -INFINITY, mx1 = -INFINITY;
#pragma unroll
            for (int t = 0; t < 8; t++) {
                mx0 = fmaxf(mx0, fmaxf(s[t][0], s[t][1]));
                mx1 = fmaxf(mx1, fmaxf(s[t][2], s[t][3]));
            }
#pragma unroll
            for (int off = 1; off <= 2; off <<= 1) {
                mx0 = fmaxf(mx0, __shfl_xor_sync(0xffffffffu, mx0, off));
                mx1 = fmaxf(mx1, __shfl_xor_sync(0xffffffffu, mx1, off));
            }
            float mn0 = fmaxf(m0, mx0), mn1 = fmaxf(m1, mx1);
            float al0 = exp2f(m0 - mn0), al1 = exp2f(m1 - mn1);
            m0 = mn0; m1 = mn1;
#pragma unroll
            for (int t = 0; t < 8; t++) {
                o[t][0] *= al0; o[t][1] *= al0;
                o[t][2] *= al1; o[t][3] *= al1;
            }
            lacc[0] *= al0; lacc[1] *= al0;
            lacc[2] *= al1; lacc[3] *= al1;

            const int vrow0 = lane & 15;
            const int vcoff = (lane >> 4) * 8;
#pragma unroll
            for (int j = 0; j < 4; j++) {
                // P = 2^(s - m) directly in f16x2 (log2-domain logits)
                uint32_t ph[4];
                ph[0] = h2ex2(pack2h(s[2 * j][0] - mn0, s[2 * j][1] - mn0));
                ph[1] = h2ex2(pack2h(s[2 * j][2] - mn1, s[2 * j][3] - mn1));
                ph[2] = h2ex2(pack2h(s[2 * j + 1][0] - mn0, s[2 * j + 1][1] - mn0));
                ph[3] = h2ex2(pack2h(s[2 * j + 1][2] - mn1, s[2 * j + 1][3] - mn1));
#pragma unroll
                for (int p = 0; p < 4; p++) {
                    uint32_t vs[4];
                    uint32_t vo = (uint32_t)((j * 16 + vrow0) * AROWB +
                                             (16 * p + vcoff) * 2);
                    ldsm4t(vs, base + KVTILE + vo);
                    mma16816(o[2 * p],     ph, &vs[0]);
                    mma16816(o[2 * p + 1], ph, &vs[2]);
                }
                // l += P @ ones (padding col 64)
                uint32_t vone[2];
                ldsm2t(vone, base + KVTILE +
                       (uint32_t)((j * 16 + (lane & 15)) * AROWB + 128));
                mma16816(lacc, ph, vone);
            }
        }
        __syncthreads();
        if (++st == 3) st = 0;
    }

    // l broadcast: col 64 lives in lanes with (lane&3)==0
    float l0 = __shfl_sync(0xffffffffu, lacc[0], lane & 28);
    float l1 = __shfl_sync(0xffffffffu, lacc[2], lane & 28);
    const float inv0 = 1.f / l0, inv1 = 1.f / l1;
    const size_t row = rowbase + q0 + w * 16 + (lane >> 2);
    const size_t col = headoff + (lane & 3) * 2;
#pragma unroll
    for (int t = 0; t < 8; t++) {
        *(uint32_t*)&Oh[row * E_ + col + t * 8] =
            pack2h(o[t][0] * inv0, o[t][1] * inv0);
        *(uint32_t*)&Oh[(row + 8) * E_ + col + t * 8] =
            pack2h(o[t][2] * inv1, o[t][3] * inv1);
    }
}

// ---------------------------------------------------------------------------
extern "C" void kernel_launch(void* const* d_in, const int* in_sizes, int n_in,
                              void* d_out, int out_size) {
    const float* q_in = (const float*)d_in[0];
    const float* k_in = (const float*)d_in[1];
    const float* v_in = (const float*)d_in[2];
    const float* Wq = (const float*)d_in[3];
    const float* Wk = (const float*)d_in[4];
    const float* Wv = (const float*)d_in[5];
    const float* Wo = (const float*)d_in[6];
    float* out = (float*)d_out;

    __half* hA;
    cudaGetSymbolAddress((void**)&hA, g_hA);

    cudaFuncSetAttribute(gemm_qkv, cudaFuncAttributeMaxDynamicSharedMemorySize,
                         GEMM_SMEM);
    cudaFuncSetAttribute(gemm_o, cudaFuncAttributeMaxDynamicSharedMemorySize,
                         GEMM_SMEM);
    cudaFuncSetAttribute(flash_attn_tc,
                         cudaFuncAttributeMaxDynamicSharedMemorySize, ATTN_SMEM);

    // 0: setup (counters + rope table)
    setup_kernel<<<(S_ * 32) / 256, 256>>>();
    // 1: all converts (weights + activations, single fp16, 16 floats/thread)
    conv_all<<<(WCH16 + ACH16) / 256, 256>>>(Wq, Wk, Wv, Wo,
                                             q_in, k_in, v_in);
    // 2: fused persistent Q/K/V projections with register-local rope
    gemm_qkv<<<304, 256, GEMM_SMEM>>>();
    // 3: attention (log2-domain softmax, f16x2 ex2, l via ones-MMA)
    flash_attn_tc<<<dim3(S_ / 128, H_, B_), 256, ATTN_SMEM>>>(hA);
    // 4: persistent output projection
    gemm_o<<<304, 256, GEMM_SMEM>>>(out);
}